// round 1
// baseline (speedup 1.0000x reference)
#include <cuda_runtime.h>
#include <math.h>

// ---------------- problem constants ----------------
// B=4, N=4096 (64x64), C=192, NH=3, HD=64
// branches: K_SPA = {8,4,2} -> sides {57,61,63}, m = side^2
#define SCALE_F 0.07216878364870323f   // 192^-0.5

// ---------------- device scratch ----------------
__device__ float g_wtq [192*192];
__device__ float g_wtkv[192*192];
__device__ float g_wtnn[192*192];
__device__ float g_wc  [192*192*64];      // transposed conv weights (max K=8)
__device__ float g_q   [4*4096*192];      // q projection (B,N,C)
__device__ float g_t   [4*3969*192];      // sr-conv output, then LN+GELU (B,m,C)
__device__ float g_kv  [4*3969*128];      // k (0:64) and v (64:128)
__device__ float g_v2  [4*3969*64];       // v + depthwise conv
__device__ float g_xcat[4*4096*192];      // concat of 3 attention outputs

// ---------------- weight transposes ----------------
__global__ void transpose_w(const float* __restrict__ w, float* __restrict__ wt,
                            int nout, int kin)
{
    int i = blockIdx.x * 256 + threadIdx.x;
    if (i < nout * kin) {
        int j = i / kin;
        int k = i % kin;
        wt[k * nout + j] = w[i];
    }
}

// sr conv weights (co,ci,ky,kx) -> wc[(kk*192+ci)*192+co]
__global__ void conv_wt(const float* __restrict__ w, float* __restrict__ wt, int Ks)
{
    int total = 192 * 192 * Ks * Ks;
    int idx = blockIdx.x * 256 + threadIdx.x;
    if (idx >= total) return;
    int co  = idx / (192 * Ks * Ks);
    int rem = idx % (192 * Ks * Ks);
    int ci  = rem / (Ks * Ks);
    int kk  = rem % (Ks * Ks);
    wt[((size_t)kk * 192 + ci) * 192 + co] = w[idx];
}

// ---------------- GEMM: C[i][j] = sum_k A[i][k]*Wt[k][j] + bias[j] ----------------
// tile 128(M) x 64(N), BK=16, 256 threads, 8x4 per-thread microtile
__global__ void __launch_bounds__(256) gemm128x64(
    const float* __restrict__ A, const float* __restrict__ Wt,
    const float* __restrict__ bias, float* __restrict__ Cm,
    int M, int K, int ldw, int ldc)
{
    __shared__ float As[16][132];
    __shared__ float Bs[16][68];
    int t = threadIdx.x;
    int rowBase = blockIdx.x * 128;
    int colBase = blockIdx.y * 64;
    int ty = t >> 4, tx = t & 15;
    float acc[8][4] = {};

    for (int k0 = 0; k0 < K; k0 += 16) {
#pragma unroll
        for (int u = 0; u < 2; u++) {
            int r  = (t >> 2) + u * 64;
            int ar = rowBase + r;
            if (ar > M - 1) ar = M - 1;
            const float4 a4 = *(const float4*)&A[(size_t)ar * K + k0 + (t & 3) * 4];
            int ks = (t & 3) * 4;
            As[ks + 0][r] = a4.x; As[ks + 1][r] = a4.y;
            As[ks + 2][r] = a4.z; As[ks + 3][r] = a4.w;
        }
        {
            int j = t & 63;
            int kk0 = (t >> 6) * 4;
#pragma unroll
            for (int u = 0; u < 4; u++)
                Bs[kk0 + u][j] = Wt[(size_t)(k0 + kk0 + u) * ldw + colBase + j];
        }
        __syncthreads();
#pragma unroll
        for (int kk = 0; kk < 16; kk++) {
            float4 a0 = *(const float4*)&As[kk][ty * 8];
            float4 a1 = *(const float4*)&As[kk][ty * 8 + 4];
            float4 b  = *(const float4*)&Bs[kk][tx * 4];
            float av[8] = {a0.x, a0.y, a0.z, a0.w, a1.x, a1.y, a1.z, a1.w};
            float bv[4] = {b.x, b.y, b.z, b.w};
#pragma unroll
            for (int i = 0; i < 8; i++)
#pragma unroll
                for (int j = 0; j < 4; j++)
                    acc[i][j] += av[i] * bv[j];
        }
        __syncthreads();
    }
#pragma unroll
    for (int i = 0; i < 8; i++) {
        int row = rowBase + ty * 8 + i;
        if (row < M) {
            int col = colBase + tx * 4;
            float4 o;
            o.x = acc[i][0] + bias[col + 0];
            o.y = acc[i][1] + bias[col + 1];
            o.z = acc[i][2] + bias[col + 2];
            o.w = acc[i][3] + bias[col + 3];
            *(float4*)&Cm[(size_t)row * ldc + col] = o;
        }
    }
}

// ---------------- sr conv as implicit GEMM ----------------
// output tile: 128 pixels (16y x 8x) x 64 channels, loops over (ky,kx,c-chunks)
// x is (B, 4096, 192) channel-last; writes t as (B, m, 192)
__global__ void __launch_bounds__(256) conv_sr(
    const float* __restrict__ x, const float* __restrict__ wc,
    const float* __restrict__ bias, float* __restrict__ tout,
    int Ks, int side, int ntx)
{
    __shared__ float As[16][132];
    __shared__ float Bs[16][68];
    int t = threadIdx.x;
    int b = blockIdx.z;
    int coBase = blockIdx.y * 64;
    int tileY = (blockIdx.x / ntx) * 16;
    int tileX = (blockIdx.x % ntx) * 8;
    int ty = t >> 4, tx = t & 15;
    float acc[8][4] = {};

    int nkk = Ks * Ks;
    for (int kk_pos = 0; kk_pos < nkk; kk_pos++) {
        int ky = kk_pos / Ks, kx = kk_pos % Ks;
        for (int c0 = 0; c0 < 192; c0 += 16) {
#pragma unroll
            for (int u = 0; u < 2; u++) {
                int p  = (t >> 2) + u * 64;
                int py = tileY + (p >> 3); if (py > side - 1) py = side - 1;
                int px = tileX + (p & 7);  if (px > side - 1) px = side - 1;
                int gy = py + ky, gx = px + kx;
                const float4 a4 = *(const float4*)
                    &x[((size_t)(b * 4096 + gy * 64 + gx)) * 192 + c0 + (t & 3) * 4];
                int ks = (t & 3) * 4;
                As[ks + 0][p] = a4.x; As[ks + 1][p] = a4.y;
                As[ks + 2][p] = a4.z; As[ks + 3][p] = a4.w;
            }
            {
                int j = t & 63;
                int kk0 = (t >> 6) * 4;
                const float* wr = &wc[((size_t)kk_pos * 192 + c0) * 192 + coBase];
#pragma unroll
                for (int u = 0; u < 4; u++)
                    Bs[kk0 + u][j] = wr[(size_t)(kk0 + u) * 192 + j];
            }
            __syncthreads();
#pragma unroll
            for (int kk = 0; kk < 16; kk++) {
                float4 a0 = *(const float4*)&As[kk][ty * 8];
                float4 a1 = *(const float4*)&As[kk][ty * 8 + 4];
                float4 bq = *(const float4*)&Bs[kk][tx * 4];
                float av[8] = {a0.x, a0.y, a0.z, a0.w, a1.x, a1.y, a1.z, a1.w};
                float bv[4] = {bq.x, bq.y, bq.z, bq.w};
#pragma unroll
                for (int i = 0; i < 8; i++)
#pragma unroll
                    for (int j = 0; j < 4; j++)
                        acc[i][j] += av[i] * bv[j];
            }
            __syncthreads();
        }
    }
#pragma unroll
    for (int i = 0; i < 8; i++) {
        int p  = ty * 8 + i;
        int py = tileY + (p >> 3);
        int px = tileX + (p & 7);
        if (py < side && px < side) {
            int col = coBase + tx * 4;
            float4 o;
            o.x = acc[i][0] + bias[col + 0];
            o.y = acc[i][1] + bias[col + 1];
            o.z = acc[i][2] + bias[col + 2];
            o.w = acc[i][3] + bias[col + 3];
            *(float4*)&tout[((size_t)(b * side * side + py * side + px)) * 192 + col] = o;
        }
    }
}

// ---------------- LayerNorm + exact GELU, in place, one warp per row ----------------
__global__ void ln_gelu(float* __restrict__ tbuf, const float* __restrict__ g,
                        const float* __restrict__ bb, int rows)
{
    int warp = threadIdx.x >> 5, lane = threadIdx.x & 31;
    int row = blockIdx.x * 8 + warp;
    if (row >= rows) return;
    float* rp = tbuf + (size_t)row * 192;
    float v[6];
    float s = 0.f;
#pragma unroll
    for (int i = 0; i < 6; i++) { v[i] = rp[lane + i * 32]; s += v[i]; }
#pragma unroll
    for (int o = 16; o; o >>= 1) s += __shfl_xor_sync(0xffffffffu, s, o);
    float mean = s * (1.0f / 192.0f);
    float vs = 0.f;
#pragma unroll
    for (int i = 0; i < 6; i++) { float d = v[i] - mean; vs += d * d; }
#pragma unroll
    for (int o = 16; o; o >>= 1) vs += __shfl_xor_sync(0xffffffffu, vs, o);
    float inv = rsqrtf(vs * (1.0f / 192.0f) + 1e-5f);
#pragma unroll
    for (int i = 0; i < 6; i++) {
        int c = lane + i * 32;
        float y = (v[i] - mean) * inv * g[c] + bb[c];
        rp[c] = 0.5f * y * (1.0f + erff(y * 0.70710678118654752f));
    }
}

// ---------------- depthwise 3x3 on v, v2 = v + dwconv(v) ----------------
__global__ void dw3x3(const float* __restrict__ kv, const float* __restrict__ w,
                      const float* __restrict__ bias, float* __restrict__ v2,
                      int side, int m)
{
    int idx = blockIdx.x * 256 + threadIdx.x;
    int total = 4 * m * 64;
    if (idx >= total) return;
    int d  = idx & 63;
    int rp = idx >> 6;
    int p  = rp % m;
    int b  = rp / m;
    int y = p / side, xx = p % side;
    float s = bias[d];
#pragma unroll
    for (int dy = 0; dy < 3; dy++) {
        int yy = y + dy - 1;
        if (yy < 0 || yy >= side) continue;
#pragma unroll
        for (int dx = 0; dx < 3; dx++) {
            int xc = xx + dx - 1;
            if (xc < 0 || xc >= side) continue;
            s += kv[((size_t)(b * m + yy * side + xc)) * 128 + 64 + d] * w[d * 9 + dy * 3 + dx];
        }
    }
    v2[idx] = kv[((size_t)(b * m + p)) * 128 + 64 + d] + s;
}

// ---------------- flash attention: 64 queries/block vs m keys ----------------
// QK and PV as 4x4-microtile smem GEMMs; online softmax with 4-thread row groups.
__global__ void __launch_bounds__(256) attn64(
    const float* __restrict__ qbuf, const float* __restrict__ kv,
    const float* __restrict__ v2, float* __restrict__ xcat,
    int m, int head)
{
    extern __shared__ float smx[];
    float* Qst = smx;                 // [64 d][68]: Qst[d*68+q]
    float* Kst = smx + 64 * 68;       // [64 d][68]: Kst[d*68+k]
    float* Vs  = smx + 2 * 64 * 68;   // [64 k][68]: Vs[k*68+d]
    float* Ps  = smx + 3 * 64 * 68;   // [64 k][68]: Ps[k*68+q]  (transposed P)
    __shared__ float corrs[64];
    __shared__ float sinv[64];

    int t = threadIdx.x;
    int b = blockIdx.y;
    int n0 = blockIdx.x * 64;
    int ty = t >> 4, tx = t & 15;
    int qrole = t >> 2, lane4 = t & 3;

    // load Q transposed
#pragma unroll
    for (int r = 0; r < 16; r++) {
        int e = t + r * 256;
        int qq = e >> 6, d = e & 63;
        Qst[d * 68 + qq] = qbuf[((size_t)(b * 4096 + n0 + qq)) * 192 + head * 64 + d];
    }

    float Mi = -1e30f, Ssum = 0.0f;
    float acc[4][4] = {};   // rows q=ty*4+i, cols d=tx*4+j
    int ntiles = (m + 63) / 64;

    for (int kt = 0; kt < ntiles; kt++) {
        // load K (transposed) and V (natural)
        {
            int kr = t >> 2;                 // 0..63
            int kidx = kt * 64 + kr;
            bool ok = (kidx < m);
            const float* krow = &kv[((size_t)(b * m + (ok ? kidx : 0))) * 128];
            const float* vrow = &v2[((size_t)(b * m + (ok ? kidx : 0))) * 64];
#pragma unroll
            for (int r = 0; r < 4; r++) {
                int d0 = (t & 3) * 16 + r * 4;
                float4 kq = ok ? *(const float4*)&krow[d0] : make_float4(0, 0, 0, 0);
                float4 vq = ok ? *(const float4*)&vrow[d0] : make_float4(0, 0, 0, 0);
                Kst[(d0 + 0) * 68 + kr] = kq.x; Kst[(d0 + 1) * 68 + kr] = kq.y;
                Kst[(d0 + 2) * 68 + kr] = kq.z; Kst[(d0 + 3) * 68 + kr] = kq.w;
                *(float4*)&Vs[kr * 68 + d0] = vq;
            }
        }
        __syncthreads();                            // (A)

        // GEMM1: S[q][k]
        float s[4][4] = {};
#pragma unroll
        for (int dd = 0; dd < 64; dd++) {
            float4 a  = *(const float4*)&Qst[dd * 68 + ty * 4];
            float4 bq = *(const float4*)&Kst[dd * 68 + tx * 4];
            float av[4] = {a.x, a.y, a.z, a.w};
            float bv[4] = {bq.x, bq.y, bq.z, bq.w};
#pragma unroll
            for (int i = 0; i < 4; i++)
#pragma unroll
                for (int j = 0; j < 4; j++)
                    s[i][j] += av[i] * bv[j];
        }
        // write scaled+masked scores transposed: Ps[k][q]
#pragma unroll
        for (int j = 0; j < 4; j++) {
            int kk = tx * 4 + j;
            int kidx = kt * 64 + kk;
            bool ok = (kidx < m);
#pragma unroll
            for (int i = 0; i < 4; i++)
                Ps[kk * 68 + ty * 4 + i] = ok ? s[i][j] * SCALE_F : -1e30f;
        }
        __syncthreads();                            // (B)

        // online softmax bookkeeping: 4 threads per query row
        float pv[16];
        float tm = -1e30f;
#pragma unroll
        for (int j = 0; j < 16; j++) {
            pv[j] = Ps[(lane4 + 4 * j) * 68 + qrole];
            tm = fmaxf(tm, pv[j]);
        }
        tm = fmaxf(tm, __shfl_xor_sync(0xffffffffu, tm, 1));
        tm = fmaxf(tm, __shfl_xor_sync(0xffffffffu, tm, 2));
        float newM = fmaxf(Mi, tm);
        float corr = __expf(Mi - newM);
        float psum = 0.f;
#pragma unroll
        for (int j = 0; j < 16; j++) {
            float e = __expf(pv[j] - newM);
            psum += e;
            Ps[(lane4 + 4 * j) * 68 + qrole] = e;
        }
        Ssum = Ssum * corr + psum;
        Mi = newM;
        if (lane4 == 0) corrs[qrole] = corr;
        __syncthreads();                            // (C)

        // rescale + PV
        float cr[4];
#pragma unroll
        for (int i = 0; i < 4; i++) cr[i] = corrs[ty * 4 + i];
#pragma unroll
        for (int i = 0; i < 4; i++)
#pragma unroll
            for (int j = 0; j < 4; j++) acc[i][j] *= cr[i];
#pragma unroll
        for (int kk = 0; kk < 64; kk++) {
            float4 a  = *(const float4*)&Ps[kk * 68 + ty * 4];
            float4 vv = *(const float4*)&Vs[kk * 68 + tx * 4];
            float av[4] = {a.x, a.y, a.z, a.w};
            float bv[4] = {vv.x, vv.y, vv.z, vv.w};
#pragma unroll
            for (int i = 0; i < 4; i++)
#pragma unroll
                for (int j = 0; j < 4; j++)
                    acc[i][j] += av[i] * bv[j];
        }
        __syncthreads();                            // (D)
    }

    // finalize
    Ssum += __shfl_xor_sync(0xffffffffu, Ssum, 1);
    Ssum += __shfl_xor_sync(0xffffffffu, Ssum, 2);
    if (lane4 == 0) sinv[qrole] = 1.0f / Ssum;
    __syncthreads();
#pragma unroll
    for (int i = 0; i < 4; i++) {
        int row = ty * 4 + i;
        float inv = sinv[row];
        float4 o;
        o.x = acc[i][0] * inv; o.y = acc[i][1] * inv;
        o.z = acc[i][2] * inv; o.w = acc[i][3] * inv;
        *(float4*)&xcat[((size_t)(b * 4096 + n0 + row)) * 192 + head * 64 + tx * 4] = o;
    }
}

// ---------------- launch ----------------
extern "C" void kernel_launch(void* const* d_in, const int* in_sizes, int n_in,
                              void* d_out, int out_size)
{
    (void)in_sizes; (void)n_in; (void)out_size;
    const float* x     = (const float*)d_in[0];
    const float* q_w   = (const float*)d_in[1];
    const float* q_b   = (const float*)d_in[2];
    const float* kv_w  = (const float*)d_in[3];
    const float* kv_b  = (const float*)d_in[4];
    const float* sr_w[3] = {(const float*)d_in[5], (const float*)d_in[7], (const float*)d_in[9]};
    const float* sr_b[3] = {(const float*)d_in[6], (const float*)d_in[8], (const float*)d_in[10]};
    const float* ln_g[3] = {(const float*)d_in[11], (const float*)d_in[13], (const float*)d_in[15]};
    const float* ln_b[3] = {(const float*)d_in[12], (const float*)d_in[14], (const float*)d_in[16]};
    const float* lc_w[3] = {(const float*)d_in[17], (const float*)d_in[19], (const float*)d_in[21]};
    const float* lc_b[3] = {(const float*)d_in[18], (const float*)d_in[20], (const float*)d_in[22]};
    const float* nn1_w = (const float*)d_in[23];
    const float* nn1_b = (const float*)d_in[24];
    float* out = (float*)d_out;

    float *p_wtq, *p_wtkv, *p_wtnn, *p_wc, *p_q, *p_t, *p_kv, *p_v2, *p_xcat;
    cudaGetSymbolAddress((void**)&p_wtq,  g_wtq);
    cudaGetSymbolAddress((void**)&p_wtkv, g_wtkv);
    cudaGetSymbolAddress((void**)&p_wtnn, g_wtnn);
    cudaGetSymbolAddress((void**)&p_wc,   g_wc);
    cudaGetSymbolAddress((void**)&p_q,    g_q);
    cudaGetSymbolAddress((void**)&p_t,    g_t);
    cudaGetSymbolAddress((void**)&p_kv,   g_kv);
    cudaGetSymbolAddress((void**)&p_v2,   g_v2);
    cudaGetSymbolAddress((void**)&p_xcat, g_xcat);

    cudaFuncSetAttribute(attn64, cudaFuncAttributeMaxDynamicSharedMemorySize, 4 * 64 * 68 * 4);

    // weight transposes
    transpose_w<<<(192 * 192 + 255) / 256, 256>>>(q_w,  p_wtq,  192, 192);
    transpose_w<<<(192 * 192 + 255) / 256, 256>>>(kv_w, p_wtkv, 192, 192);
    transpose_w<<<(192 * 192 + 255) / 256, 256>>>(nn1_w, p_wtnn, 192, 192);

    // q projection: (16384 x 192) @ (192 x 192)
    gemm128x64<<<dim3(128, 3), 256>>>(x, p_wtq, q_b, p_q, 16384, 192, 192, 192);

    const int Ksz[3]  = {8, 4, 2};
    const int sideA[3] = {57, 61, 63};

    for (int br = 0; br < 3; br++) {
        int side = sideA[br], Ks = Ksz[br], m = side * side;
        int rows = 4 * m;
        int ntx = (side + 7) / 8;
        int nty = (side + 15) / 16;

        conv_wt<<<(192 * 192 * Ks * Ks + 255) / 256, 256>>>(sr_w[br], p_wc, Ks);
        conv_sr<<<dim3(nty * ntx, 3, 4), 256>>>(x, p_wc, sr_b[br], p_t, Ks, side, ntx);
        ln_gelu<<<(rows + 7) / 8, 256>>>(p_t, ln_g[br], ln_b[br], rows);
        gemm128x64<<<dim3((rows + 127) / 128, 2), 256>>>(p_t, p_wtkv, kv_b, p_kv, rows, 192, 192, 128);
        dw3x3<<<(rows * 64 + 255) / 256, 256>>>(p_kv, lc_w[br], lc_b[br], p_v2, side, m);
        attn64<<<dim3(64, 4), 256, 4 * 64 * 68 * 4>>>(p_q, p_kv, p_v2, p_xcat, m, br);
    }

    // final projection
    gemm128x64<<<dim3(128, 3), 256>>>(p_xcat, p_wtnn, nn1_b, out, 16384, 192, 192, 192);
}